// round 4
// baseline (speedup 1.0000x reference)
#include <cuda_runtime.h>

#define NN 100000
#define NE 1250000
#define HID 64
#define NG 256
#define NC 10
#define TR 96            // rows per GEMM block
#define GEMM_T 96        // threads per GEMM block

// ---------------- scratch (static device globals; no allocation) ----------------
__device__ int   g_cnt_in[NN];        // in-degree (excluding self loop)
__device__ int   g_fill[NN];          // CSR fill cursors
__device__ int   g_rowstart[NN + 1];  // CSR row offsets
__device__ float g_dinv[NN];          // 1/sqrt(deg+1)
__device__ int2  g_csr[NE];           // (src, bitcast(norm)) per edge, grouped by dst
__device__ float g_hW[NN * HID];      // h @ W scratch
__device__ float g_accA[NN * HID];    // layer accumulators (ping-pong)
__device__ float g_accB[NN * HID];
__device__ float g_pool[NG * HID];    // per-graph feature sums
__device__ float g_gcnt[NG];          // per-graph node counts
__device__ int   g_is64;              // 1 if index arrays are int64, 0 if int32

// Device-side buffer selector (host must not pass __device__ symbol addresses)
__device__ __forceinline__ float* buf_sel(int which) {
    return (which == 0) ? g_hW : (which == 1) ? g_accA : g_accB;
}
__device__ __forceinline__ const float* cbuf_sel(int which) {
    return (which == 0) ? g_hW : (which == 1) ? g_accA : g_accB;
}

// Width-dispatching index load: logical element e of an int array that may be
// stored as int32 or int64.
__device__ __forceinline__ int ld_idx(const void* p, long long e) {
    if (g_is64) return (int)((const long long*)p)[e];
    return ((const int*)p)[e];
}

// ---------------- dtype detection ----------------
// If edge_index is int64 (little-endian, values < 2^31), every odd 32-bit word
// is a zero high-half. If int32, odd words are random edge indices.
__global__ void detect_kernel(const int* __restrict__ ei32) {
    if (threadIdx.x == 0 && blockIdx.x == 0) {
        int allzero = 1;
        for (int i = 1; i < 128; i += 2)
            if (ei32[i] != 0) { allzero = 0; break; }
        g_is64 = allzero;
    }
}

// ---------------- preprocessing ----------------
__global__ void init_kernel() {
    int i = blockIdx.x * blockDim.x + threadIdx.x;
    if (i < NN) { g_cnt_in[i] = 0; g_fill[i] = 0; }
    if (i < NG * HID) g_pool[i] = 0.0f;
    if (i < NG) g_gcnt[i] = 0.0f;
}

__global__ void count_kernel(const void* __restrict__ ei) {
    int e = blockIdx.x * blockDim.x + threadIdx.x;
    if (e >= NE) return;
    atomicAdd(&g_cnt_in[ld_idx(ei, (long long)NE + e)], 1);
}

__global__ void dinv_kernel() {
    int i = blockIdx.x * blockDim.x + threadIdx.x;
    if (i >= NN) return;
    g_dinv[i] = rsqrtf((float)g_cnt_in[i] + 1.0f);   // +1 for self loop; always > 0
}

// single-block exclusive scan of g_cnt_in -> g_rowstart
__global__ void scan_kernel() {
    __shared__ int wsum[32];
    const int T = 1024;
    int tid = threadIdx.x;
    const int chunk = (NN + T - 1) / T;   // 98
    int start = tid * chunk;
    int end = min(start + chunk, NN);
    int s = 0;
    for (int i = start; i < end; i++) s += g_cnt_in[i];
    int lane = tid & 31, wid = tid >> 5;
    int inc = s;
    #pragma unroll
    for (int o = 1; o < 32; o <<= 1) {
        int u = __shfl_up_sync(0xffffffffu, inc, o);
        if (lane >= o) inc += u;
    }
    if (lane == 31) wsum[wid] = inc;
    __syncthreads();
    if (wid == 0) {
        int v = wsum[lane];
        #pragma unroll
        for (int o = 1; o < 32; o <<= 1) {
            int u = __shfl_up_sync(0xffffffffu, v, o);
            if (lane >= o) v += u;
        }
        wsum[lane] = v;
    }
    __syncthreads();
    int run = inc - s + (wid > 0 ? wsum[wid - 1] : 0);
    for (int i = start; i < end; i++) {
        g_rowstart[i] = run;
        run += g_cnt_in[i];
    }
    if (tid == 0) g_rowstart[NN] = NE;
}

__global__ void fill_kernel(const void* __restrict__ ei) {
    int e = blockIdx.x * blockDim.x + threadIdx.x;
    if (e >= NE) return;
    int s = ld_idx(ei, e);
    int d = ld_idx(ei, (long long)NE + e);
    int pos = g_rowstart[d] + atomicAdd(&g_fill[d], 1);
    float w = g_dinv[s] * g_dinv[d];
    g_csr[pos] = make_int2(s, __float_as_int(w));
}

// ---------------- fused GEMM: g_hW = act(in (+bias)) @ W ----------------
// 96 rows x 64 cols per block, 96 threads, 8x8 register tile each.
__global__ void __launch_bounds__(GEMM_T) gemm_kernel(
    const float* __restrict__ in_ext, int in_sel,
    const float* __restrict__ bias,
    const float* __restrict__ W)
{
    __shared__ float sInT[64 * 100];   // [k][r], stride 100 (pad: conflict-free, 16B aligned)
    __shared__ float sW[64 * 64];      // [k][j]

    const float* in = in_ext ? in_ext : cbuf_sel(in_sel);
    float* out = g_hW;

    int tid = threadIdx.x;
    int r0 = blockIdx.x * TR;
    const bool has_bias = (bias != nullptr);

    for (int i = tid; i < 64 * 64; i += GEMM_T) sW[i] = W[i];

    for (int p = 0; p < TR * 64; p += GEMM_T) {
        int lin = p + tid;
        int r = lin >> 6;
        int k = lin & 63;
        int gr = r0 + r;
        float v = 0.0f;
        if (gr < NN) {
            v = in[gr * 64 + k];
            if (has_bias) v = fmaxf(v + bias[k], 0.0f);
        }
        sInT[k * 100 + r] = v;
    }
    __syncthreads();

    int cx = tid & 7;    // column group (8 cols)
    int ry = tid >> 3;   // row group (8 rows), 0..11

    float acc[8][8];
    #pragma unroll
    for (int i = 0; i < 8; i++)
        #pragma unroll
        for (int j = 0; j < 8; j++) acc[i][j] = 0.0f;

    #pragma unroll 4
    for (int k = 0; k < 64; k++) {
        float4 a0 = *(const float4*)&sInT[k * 100 + ry * 8];
        float4 a1 = *(const float4*)&sInT[k * 100 + ry * 8 + 4];
        float4 w0 = *(const float4*)&sW[k * 64 + cx * 8];
        float4 w1 = *(const float4*)&sW[k * 64 + cx * 8 + 4];
        float a[8] = {a0.x, a0.y, a0.z, a0.w, a1.x, a1.y, a1.z, a1.w};
        float w[8] = {w0.x, w0.y, w0.z, w0.w, w1.x, w1.y, w1.z, w1.w};
        #pragma unroll
        for (int i = 0; i < 8; i++)
            #pragma unroll
            for (int j = 0; j < 8; j++)
                acc[i][j] = fmaf(a[i], w[j], acc[i][j]);
    }

    #pragma unroll
    for (int i = 0; i < 8; i++) {
        int gr = r0 + ry * 8 + i;
        if (gr < NN) {
            float4 o0 = make_float4(acc[i][0], acc[i][1], acc[i][2], acc[i][3]);
            float4 o1 = make_float4(acc[i][4], acc[i][5], acc[i][6], acc[i][7]);
            *(float4*)&out[gr * 64 + cx * 8] = o0;
            *(float4*)&out[gr * 64 + cx * 8 + 4] = o1;
        }
    }
}

// ---------------- atomic-free CSR gather: acc[i] = dinv[i]^2*hW[i] + sum_e w_e*hW[src_e] ----
__global__ void __launch_bounds__(256) gather_kernel(int out_sel)
{
    const float* __restrict__ hW = g_hW;
    float* acc_out = buf_sel(out_sel);

    int t = blockIdx.x * blockDim.x + threadIdx.x;
    int i = t >> 4;            // node (16 threads / node)
    if (i >= NN) return;
    int c = (t & 15) << 2;     // float offset 0..60

    int beg = g_rowstart[i];
    int end = g_rowstart[i + 1];
    float di = g_dinv[i];
    float sw = di * di;

    float4 v = *(const float4*)&hW[i * 64 + c];
    float4 s = make_float4(v.x * sw, v.y * sw, v.z * sw, v.w * sw);

    int e = beg;
    for (; e + 1 < end; e += 2) {
        int2 p0 = g_csr[e];
        int2 p1 = g_csr[e + 1];
        float w0 = __int_as_float(p0.y);
        float w1 = __int_as_float(p1.y);
        float4 v0 = *(const float4*)&hW[p0.x * 64 + c];
        float4 v1 = *(const float4*)&hW[p1.x * 64 + c];
        s.x += v0.x * w0 + v1.x * w1;
        s.y += v0.y * w0 + v1.y * w1;
        s.z += v0.z * w0 + v1.z * w1;
        s.w += v0.w * w0 + v1.w * w1;
    }
    if (e < end) {
        int2 p0 = g_csr[e];
        float w0 = __int_as_float(p0.y);
        float4 v0 = *(const float4*)&hW[p0.x * 64 + c];
        s.x += v0.x * w0; s.y += v0.y * w0; s.z += v0.z * w0; s.w += v0.w * w0;
    }
    *(float4*)&acc_out[i * 64 + c] = s;
}

// ---------------- global mean pool (sum part), reads selected buffer ----------------
__global__ void __launch_bounds__(256) pool_kernel(int in_sel, const void* __restrict__ batch)
{
    const float* acc = cbuf_sel(in_sel);
    int t = blockIdx.x * blockDim.x + threadIdx.x;
    int i = t >> 4;
    if (i >= NN) return;
    int c = (t & 15) << 2;
    int g = ld_idx(batch, i);
    float4 v = *(const float4*)&acc[i * 64 + c];
    float* p = &g_pool[g * 64 + c];
    atomicAdd(p + 0, v.x);
    atomicAdd(p + 1, v.y);
    atomicAdd(p + 2, v.z);
    atomicAdd(p + 3, v.w);
    if ((t & 15) == 0) atomicAdd(&g_gcnt[g], 1.0f);
}

// ---------------- final: out[g][c] = (pool[g]/cnt + b3) @ Wlin + blin ----------------
__global__ void final_kernel(const float* __restrict__ b3,
                             const float* __restrict__ Wlin,
                             const float* __restrict__ blin,
                             float* __restrict__ out)
{
    int idx = blockIdx.x * blockDim.x + threadIdx.x;
    if (idx >= NG * NC) return;
    int g = idx / NC, c = idx % NC;
    float inv = 1.0f / fmaxf(g_gcnt[g], 1.0f);
    float sum = blin[c];
    #pragma unroll
    for (int h = 0; h < 64; h++) {
        float v = g_pool[g * 64 + h] * inv + b3[h];
        sum = fmaf(v, Wlin[h * NC + c], sum);
    }
    out[idx] = sum;
}

// ---------------- launch ----------------
extern "C" void kernel_launch(void* const* d_in, const int* in_sizes, int n_in,
                              void* d_out, int out_size)
{
    const float* x     = (const float*)d_in[0];
    const void*  ei    = d_in[1];
    const void*  batch = d_in[2];
    const float* W1 = (const float*)d_in[3];
    const float* b1 = (const float*)d_in[4];
    const float* W2 = (const float*)d_in[5];
    const float* b2 = (const float*)d_in[6];
    const float* W3 = (const float*)d_in[7];
    const float* b3 = (const float*)d_in[8];
    const float* Wlin = (const float*)d_in[9];
    const float* blin = (const float*)d_in[10];
    float* out = (float*)d_out;

    const int nB = (NN + 255) / 256;
    const int eB = (NE + 255) / 256;
    const int gemmB = (NN + TR - 1) / TR;
    const int gatB = (NN * 16 + 255) / 256;

    // dtype sniff + preprocessing: degree -> dinv -> CSR by destination
    detect_kernel<<<1, 32>>>((const int*)ei);
    init_kernel<<<nB, 256>>>();
    count_kernel<<<eB, 256>>>(ei);
    dinv_kernel<<<nB, 256>>>();
    scan_kernel<<<1, 1024>>>();
    fill_kernel<<<eB, 256>>>(ei);

    // layer 1: hW = x @ W1 ; accA = A_hat hW
    gemm_kernel<<<gemmB, GEMM_T>>>(x, -1, nullptr, W1);
    gather_kernel<<<gatB, 256>>>(1);
    // layer 2: hW = relu(accA + b1) @ W2 ; accB = A_hat hW
    gemm_kernel<<<gemmB, GEMM_T>>>(nullptr, 1, b1, W2);
    gather_kernel<<<gatB, 256>>>(2);
    // layer 3: hW = relu(accB + b2) @ W3 ; accA = A_hat hW
    gemm_kernel<<<gemmB, GEMM_T>>>(nullptr, 2, b2, W3);
    gather_kernel<<<gatB, 256>>>(1);

    // mean pool + classifier (b3 folded into final kernel)
    pool_kernel<<<gatB, 256>>>(1, batch);
    final_kernel<<<(NG * NC + 255) / 256, 256>>>(b3, Wlin, blin, out);
}

// round 6
// speedup vs baseline: 1.5212x; 1.5212x over previous
#include <cuda_runtime.h>

#define NN 100000
#define NE 1250000
#define HID 64
#define NG 256
#define NC 10
#define TR 128           // rows per GEMM block
#define GEMM_T 256       // threads per GEMM block
#define NBLK 391         // ceil(NN/256)
#define GEMM_SMEM_BYTES (TR * 68 * 4 + 64 * 64 * 4)   // sIn + sW = 51200

typedef unsigned long long ull;

// ---------------- scratch (static device globals; no allocation) ----------------
__device__ int   g_cnt_in[NN];        // in-degree (excluding self loop)
__device__ int   g_fill[NN];          // CSR fill cursors
__device__ int   g_rowstart[NN + 1];  // CSR row offsets
__device__ float g_dinv[NN];          // 1/sqrt(deg+1)
__device__ int   g_bsum[NBLK];        // per-block degree sums
__device__ int   g_boff[NBLK];        // exclusive block offsets
__device__ int2  g_csr[NE];           // (src, bitcast(norm)) per edge, grouped by dst
__device__ float g_hW[NN * HID];      // h @ W scratch
__device__ float g_accA[NN * HID];    // layer accumulators (ping-pong)
__device__ float g_accB[NN * HID];
__device__ float g_pool[NG * HID];    // per-graph feature sums
__device__ float g_gcnt[NG];          // per-graph node counts
__device__ int   g_is64;              // 1 if index arrays are int64, 0 if int32

__device__ __forceinline__ float* buf_sel(int which) {
    return (which == 0) ? g_hW : (which == 1) ? g_accA : g_accB;
}
__device__ __forceinline__ const float* cbuf_sel(int which) {
    return (which == 0) ? g_hW : (which == 1) ? g_accA : g_accB;
}

__device__ __forceinline__ int ld_idx(const void* p, long long e) {
    if (g_is64) return (int)((const long long*)p)[e];
    return ((const int*)p)[e];
}

// packed f32x2 helpers (FFMA2 — ptxas never emits this from C++)
__device__ __forceinline__ ull ffma2(ull a, ull b, ull c) {
    ull d;
    asm("fma.rn.f32x2 %0, %1, %2, %3;" : "=l"(d) : "l"(a), "l"(b), "l"(c));
    return d;
}
__device__ __forceinline__ ull bcast2(float x) {
    ull d;
    asm("mov.b64 %0, {%1, %1};" : "=l"(d) : "f"(x));
    return d;
}

// ---------------- dtype detection ----------------
__global__ void detect_kernel(const int* __restrict__ ei32) {
    if (threadIdx.x == 0 && blockIdx.x == 0) {
        int allzero = 1;
        for (int i = 1; i < 128; i += 2)
            if (ei32[i] != 0) { allzero = 0; break; }
        g_is64 = allzero;
    }
}

// ---------------- preprocessing ----------------
__global__ void init_kernel() {
    int i = blockIdx.x * blockDim.x + threadIdx.x;
    if (i < NN) g_cnt_in[i] = 0;
}

__global__ void count_kernel(const void* __restrict__ ei) {
    int e = blockIdx.x * blockDim.x + threadIdx.x;
    if (e >= NE) return;
    atomicAdd(&g_cnt_in[ld_idx(ei, (long long)NE + e)], 1);
}

// pass 1: per-block degree sums (+dinv fused)
__global__ void blocksum_kernel() {
    __shared__ int sred[256];
    int i = blockIdx.x * 256 + threadIdx.x;
    int v = (i < NN) ? g_cnt_in[i] : 0;
    if (i < NN) g_dinv[i] = rsqrtf((float)v + 1.0f);
    sred[threadIdx.x] = v;
    __syncthreads();
    for (int h = 128; h > 0; h >>= 1) {
        if (threadIdx.x < h) sred[threadIdx.x] += sred[threadIdx.x + h];
        __syncthreads();
    }
    if (threadIdx.x == 0) g_bsum[blockIdx.x] = sred[0];
}

// pass 2: single-block scan of 391 block sums -> exclusive offsets
__global__ void scanb_kernel() {
    __shared__ int s[512];
    int t = threadIdx.x;
    s[t] = (t < NBLK) ? g_bsum[t] : 0;
    __syncthreads();
    for (int off = 1; off < 512; off <<= 1) {
        int v = (t >= off) ? s[t - off] : 0;
        __syncthreads();
        s[t] += v;
        __syncthreads();
    }
    if (t < NBLK) g_boff[t] = s[t] - g_bsum[t];   // exclusive
}

// pass 3: per-block exclusive scan + block offset -> rowstart (+fill zero fused)
__global__ void rowstart_kernel() {
    __shared__ int s[256];
    int t = threadIdx.x;
    int i = blockIdx.x * 256 + t;
    int own = (i < NN) ? g_cnt_in[i] : 0;
    s[t] = own;
    __syncthreads();
    for (int off = 1; off < 256; off <<= 1) {
        int v = (t >= off) ? s[t - off] : 0;
        __syncthreads();
        s[t] += v;
        __syncthreads();
    }
    if (i < NN) {
        g_rowstart[i] = g_boff[blockIdx.x] + s[t] - own;
        g_fill[i] = 0;
    }
    if (i == 0) g_rowstart[NN] = NE;
}

__global__ void fill_kernel(const void* __restrict__ ei) {
    int e = blockIdx.x * blockDim.x + threadIdx.x;
    if (e >= NE) return;
    int s = ld_idx(ei, e);
    int d = ld_idx(ei, (long long)NE + e);
    int pos = g_rowstart[d] + atomicAdd(&g_fill[d], 1);
    float w = g_dinv[s] * g_dinv[d];
    g_csr[pos] = make_int2(s, __float_as_int(w));
}

// ---------------- fused GEMM: g_hW = act(in (+bias)) @ W ----------------
// 128 rows x 64 cols per block, 256 threads, 4 rows x 8 cols per thread, FFMA2.
// Dynamic smem (51200 B > 48K static limit).
__global__ void __launch_bounds__(GEMM_T) gemm_kernel(
    const float* __restrict__ in_ext, int in_sel,
    const float* __restrict__ bias,
    const float* __restrict__ W)
{
    extern __shared__ float smem[];
    float* sIn = smem;                 // [r][k], stride 68 (16B-aligned, 2-way max conflict)
    float* sW  = smem + TR * 68;       // [k][j]

    const float* in = in_ext ? in_ext : cbuf_sel(in_sel);
    float* out = g_hW;

    int tid = threadIdx.x;
    int r0 = blockIdx.x * TR;
    const bool has_bias = (bias != nullptr);

    // load W (coalesced float4)
    for (int q = tid; q < 64 * 16; q += GEMM_T) {
        int kk = q >> 4, j4 = q & 15;
        *(float4*)&sW[kk * 64 + j4 * 4] = *(const float4*)&W[kk * 64 + j4 * 4];
    }
    // load A rows (coalesced float4, bias+relu fused)
    for (int q = tid; q < TR * 16; q += GEMM_T) {
        int r = q >> 4, k4 = q & 15;
        int gr = r0 + r;
        float4 v = make_float4(0.f, 0.f, 0.f, 0.f);
        if (gr < NN) {
            v = *(const float4*)&in[gr * 64 + k4 * 4];
            if (has_bias) {
                v.x = fmaxf(v.x + bias[k4 * 4 + 0], 0.f);
                v.y = fmaxf(v.y + bias[k4 * 4 + 1], 0.f);
                v.z = fmaxf(v.z + bias[k4 * 4 + 2], 0.f);
                v.w = fmaxf(v.w + bias[k4 * 4 + 3], 0.f);
            }
        }
        *(float4*)&sIn[r * 68 + k4 * 4] = v;
    }
    __syncthreads();

    const int cx = tid & 7;            // col group (8 cols)
    const int ry4 = (tid >> 3) * 4;    // first of 4 rows

    ull acc[4][4] = {};                // [row][colpair], f32x2 each

    #pragma unroll 4
    for (int k = 0; k < 64; k++) {
        const ulonglong2* wp = (const ulonglong2*)&sW[k * 64 + cx * 8];
        ulonglong2 wa = wp[0];         // cols {0,1},{2,3}
        ulonglong2 wb = wp[1];         // cols {4,5},{6,7}
        #pragma unroll
        for (int i = 0; i < 4; i++) {
            ull a2 = bcast2(sIn[(ry4 + i) * 68 + k]);
            acc[i][0] = ffma2(a2, wa.x, acc[i][0]);
            acc[i][1] = ffma2(a2, wa.y, acc[i][1]);
            acc[i][2] = ffma2(a2, wb.x, acc[i][2]);
            acc[i][3] = ffma2(a2, wb.y, acc[i][3]);
        }
    }

    #pragma unroll
    for (int i = 0; i < 4; i++) {
        int gr = r0 + ry4 + i;
        if (gr < NN) {
            union { ull u[4]; float4 f[2]; } row;
            row.u[0] = acc[i][0]; row.u[1] = acc[i][1];
            row.u[2] = acc[i][2]; row.u[3] = acc[i][3];
            *(float4*)&out[gr * 64 + cx * 8]     = row.f[0];
            *(float4*)&out[gr * 64 + cx * 8 + 4] = row.f[1];
        }
    }
}

// ---------------- atomic-free CSR gather ----------------
__global__ void __launch_bounds__(256) gather_kernel(int out_sel)
{
    const float* __restrict__ hW = g_hW;
    float* acc_out = buf_sel(out_sel);

    int t = blockIdx.x * blockDim.x + threadIdx.x;
    int i = t >> 4;            // node (16 threads / node)
    if (i >= NN) return;
    int c = (t & 15) << 2;     // float offset 0..60

    int beg = g_rowstart[i];
    int end = g_rowstart[i + 1];
    float di = g_dinv[i];
    float sw = di * di;

    float4 v = *(const float4*)&hW[i * 64 + c];
    float4 s0 = make_float4(v.x * sw, v.y * sw, v.z * sw, v.w * sw);
    float4 s1 = make_float4(0.f, 0.f, 0.f, 0.f);

    int e = beg;
    for (; e + 3 < end; e += 4) {
        int2 p0 = g_csr[e];
        int2 p1 = g_csr[e + 1];
        int2 p2 = g_csr[e + 2];
        int2 p3 = g_csr[e + 3];
        float w0 = __int_as_float(p0.y), w1 = __int_as_float(p1.y);
        float w2 = __int_as_float(p2.y), w3 = __int_as_float(p3.y);
        float4 v0 = *(const float4*)&hW[p0.x * 64 + c];
        float4 v1 = *(const float4*)&hW[p1.x * 64 + c];
        float4 v2 = *(const float4*)&hW[p2.x * 64 + c];
        float4 v3 = *(const float4*)&hW[p3.x * 64 + c];
        s0.x += v0.x * w0 + v1.x * w1;  s1.x += v2.x * w2 + v3.x * w3;
        s0.y += v0.y * w0 + v1.y * w1;  s1.y += v2.y * w2 + v3.y * w3;
        s0.z += v0.z * w0 + v1.z * w1;  s1.z += v2.z * w2 + v3.z * w3;
        s0.w += v0.w * w0 + v1.w * w1;  s1.w += v2.w * w2 + v3.w * w3;
    }
    for (; e < end; e++) {
        int2 p0 = g_csr[e];
        float w0 = __int_as_float(p0.y);
        float4 v0 = *(const float4*)&hW[p0.x * 64 + c];
        s0.x += v0.x * w0; s0.y += v0.y * w0; s0.z += v0.z * w0; s0.w += v0.w * w0;
    }
    float4 s = make_float4(s0.x + s1.x, s0.y + s1.y, s0.z + s1.z, s0.w + s1.w);
    *(float4*)&acc_out[i * 64 + c] = s;
}

// ---------------- segmented mean pool (batch is sorted; no atomics) ----------------
__global__ void __launch_bounds__(256) pool_kernel(int in_sel, const void* __restrict__ batch)
{
    __shared__ float4 sP[16][16];      // [chunk][c4]
    const float* acc = cbuf_sel(in_sel);
    int g = blockIdx.x;
    int tid = threadIdx.x;
    int chunk = tid >> 4;
    int c4 = tid & 15;

    // binary search graph bounds (batch sorted ascending)
    int lo = 0, hi = NN;
    while (lo < hi) { int mid = (lo + hi) >> 1; if (ld_idx(batch, mid) < g) lo = mid + 1; else hi = mid; }
    int start = lo;
    lo = start; hi = NN;
    while (lo < hi) { int mid = (lo + hi) >> 1; if (ld_idx(batch, mid) < g + 1) lo = mid + 1; else hi = mid; }
    int end = lo;

    float4 sum = make_float4(0.f, 0.f, 0.f, 0.f);
    for (int n = start + chunk; n < end; n += 16) {
        float4 v = *(const float4*)&acc[n * 64 + c4 * 4];
        sum.x += v.x; sum.y += v.y; sum.z += v.z; sum.w += v.w;
    }
    sP[chunk][c4] = sum;
    __syncthreads();
    for (int h = 8; h > 0; h >>= 1) {
        if (chunk < h) {
            float4 a = sP[chunk][c4], b = sP[chunk + h][c4];
            sP[chunk][c4] = make_float4(a.x + b.x, a.y + b.y, a.z + b.z, a.w + b.w);
        }
        __syncthreads();
    }
    if (chunk == 0) *(float4*)&g_pool[g * 64 + c4 * 4] = sP[0][c4];
    if (tid == 0) g_gcnt[g] = (float)(end - start);
}

// ---------------- final: out[g][c] = (pool[g]/cnt + b3) @ Wlin + blin ----------------
__global__ void final_kernel(const float* __restrict__ b3,
                             const float* __restrict__ Wlin,
                             const float* __restrict__ blin,
                             float* __restrict__ out)
{
    int idx = blockIdx.x * blockDim.x + threadIdx.x;
    if (idx >= NG * NC) return;
    int g = idx / NC, c = idx % NC;
    float inv = 1.0f / fmaxf(g_gcnt[g], 1.0f);
    float sum = blin[c];
    #pragma unroll
    for (int h = 0; h < 64; h++) {
        float v = g_pool[g * 64 + h] * inv + b3[h];
        sum = fmaf(v, Wlin[h * NC + c], sum);
    }
    out[idx] = sum;
}

// ---------------- launch ----------------
extern "C" void kernel_launch(void* const* d_in, const int* in_sizes, int n_in,
                              void* d_out, int out_size)
{
    const float* x     = (const float*)d_in[0];
    const void*  ei    = d_in[1];
    const void*  batch = d_in[2];
    const float* W1 = (const float*)d_in[3];
    const float* b1 = (const float*)d_in[4];
    const float* W2 = (const float*)d_in[5];
    const float* b2 = (const float*)d_in[6];
    const float* W3 = (const float*)d_in[7];
    const float* b3 = (const float*)d_in[8];
    const float* Wlin = (const float*)d_in[9];
    const float* blin = (const float*)d_in[10];
    float* out = (float*)d_out;

    // Raise dynamic smem limit for the GEMM (persistent per-function attribute;
    // non-stream host API, graph-capture-legal, no allocation).
    cudaFuncSetAttribute(gemm_kernel,
                         cudaFuncAttributeMaxDynamicSharedMemorySize,
                         GEMM_SMEM_BYTES);

    const int eB = (NE + 255) / 256;
    const int gemmB = (NN + TR - 1) / TR;
    const int gatB = (NN * 16 + 255) / 256;

    // dtype sniff + CSR build (count -> 3-pass parallel scan -> fill)
    detect_kernel<<<1, 32>>>((const int*)ei);
    init_kernel<<<NBLK, 256>>>();
    count_kernel<<<eB, 256>>>(ei);
    blocksum_kernel<<<NBLK, 256>>>();
    scanb_kernel<<<1, 512>>>();
    rowstart_kernel<<<NBLK, 256>>>();
    fill_kernel<<<eB, 256>>>(ei);

    // layer 1: hW = x @ W1 ; accA = A_hat hW
    gemm_kernel<<<gemmB, GEMM_T, GEMM_SMEM_BYTES>>>(x, -1, nullptr, W1);
    gather_kernel<<<gatB, 256>>>(1);
    // layer 2: hW = relu(accA + b1) @ W2 ; accB = A_hat hW
    gemm_kernel<<<gemmB, GEMM_T, GEMM_SMEM_BYTES>>>(nullptr, 1, b1, W2);
    gather_kernel<<<gatB, 256>>>(2);
    // layer 3: hW = relu(accB + b2) @ W3 ; accA = A_hat hW
    gemm_kernel<<<gemmB, GEMM_T, GEMM_SMEM_BYTES>>>(nullptr, 2, b2, W3);
    gather_kernel<<<gatB, 256>>>(1);

    // segmented mean pool + classifier
    pool_kernel<<<NG, 256>>>(1, batch);
    final_kernel<<<(NG * NC + 255) / 256, 256>>>(b3, Wlin, blin, out);
}